// round 8
// baseline (speedup 1.0000x reference)
#include <cuda_runtime.h>
#include <cuda_bf16.h>
#include <cstdint>

#define HF 128
#define WF 192
#define NA 9
#define HW (HF*WF)               // 24576
#define NTOT (HW*NA)             // 221184
#define TOPN 6000
#define POSTN 300
#define NB 94                    // ceil(6000/64)
#define TILE_WORDS (64*NB)       // 6016
#define CAND_MAX 16384
#define CTH 512                  // collect threads (>= POSTN for final write, but loop anyway)
#define NTRI (NB*(NB+1)/2)       // 4465 triangular blocks

__constant__ float c_anchors[NA][4] = {
    {-84.f,  -40.f,  99.f,  55.f},
    {-176.f, -88.f,  191.f, 103.f},
    {-360.f, -184.f, 375.f, 199.f},
    {-56.f,  -56.f,  71.f,  71.f},
    {-120.f, -120.f, 135.f, 135.f},
    {-248.f, -248.f, 263.f, 263.f},
    {-36.f,  -80.f,  51.f,  95.f},
    {-80.f,  -168.f, 95.f,  183.f},
    {-168.f, -344.f, 183.f, 359.f}
};

// single zeroed region (one memset node)
struct ZeroBlock {
    unsigned int hist[65536];
    unsigned long long sup[NB];
};
__device__ __align__(16) ZeroBlock g_z;

__device__ unsigned int g_srt[NTOT];                 // 32-bit sortable score
__device__ __align__(16) unsigned int g_sfx[65536];  // sfx[b] = #keys in buckets > b
__device__ unsigned int g_thresh;
__device__ unsigned int g_cand_count;
__device__ __align__(16) unsigned long long g_cand[CAND_MAX];
__device__ float4 g_top_boxes[TOPN];
__device__ unsigned long long g_mask[6016 * NB];

__device__ __forceinline__ void cp_async8(void* smem_dst, const void* gmem_src) {
    unsigned int d = (unsigned int)__cvta_generic_to_shared(smem_dst);
    asm volatile("cp.async.ca.shared.global [%0], [%1], 8;" :: "r"(d), "l"(gmem_src) : "memory");
}
__device__ __forceinline__ void cp_async_commit() {
    asm volatile("cp.async.commit_group;" ::: "memory");
}
__device__ __forceinline__ void cp_async_wait0() {
    asm volatile("cp.async.wait_group 0;" ::: "memory");
}

__device__ __forceinline__ float4 decode_from_deltas(int a, int k,
                                                     float dx, float dy, float dw, float dh,
                                                     float im0, float im1, float im2,
                                                     bool* valid) {
    int xs = k >> 7;          // meshgrid 'ij' quirk: shift row k -> (x=k/128, y=k%128)
    int ys = k & 127;
    float sx = 16.f * (float)xs;
    float sy = 16.f * (float)ys;
    float ax1 = c_anchors[a][0] + sx;
    float ay1 = c_anchors[a][1] + sy;
    float ax2 = c_anchors[a][2] + sx;
    float ay2 = c_anchors[a][3] + sy;

    float w = ax2 - ax1 + 1.f;
    float h = ay2 - ay1 + 1.f;
    float cx = ax1 + 0.5f * w;
    float cy = ay1 + 0.5f * h;

    float pcx = dx * w + cx;
    float pcy = dy * h + cy;
    float pw = expf(dw) * w;
    float ph = expf(dh) * h;

    float x1 = pcx - 0.5f * pw;
    float y1 = pcy - 0.5f * ph;
    float x2 = pcx + 0.5f * pw;
    float y2 = pcy + 0.5f * ph;

    x1 = fminf(fmaxf(x1, 0.f), im1 - 1.f);
    x2 = fminf(fmaxf(x2, 0.f), im1 - 1.f);
    y1 = fminf(fmaxf(y1, 0.f), im0 - 1.f);
    y2 = fminf(fmaxf(y2, 0.f), im0 - 1.f);

    float ms = 16.f * im2;
    *valid = (x2 - x1 + 1.f >= ms) && (y2 - y1 + 1.f >= ms);
    return make_float4(x1, y1, x2, y2);
}

// ---------------- K1: sortable scores + histogram ----------------
__global__ void k_score_box(const float* __restrict__ scores,
                            const float* __restrict__ deltas,
                            const float* __restrict__ im_info) {
    int t = blockIdx.x * blockDim.x + threadIdx.x;
    if (t >= NTOT) return;
    int a = t / HW;
    int k = t - a * HW;

    float sc = scores[(NA + a) * HW + k];
    float dx = deltas[(4*a + 0) * HW + k];
    float dy = deltas[(4*a + 1) * HW + k];
    float dw = deltas[(4*a + 2) * HW + k];
    float dh = deltas[(4*a + 3) * HW + k];
    float im0 = im_info[0], im1 = im_info[1], im2 = im_info[2];
    bool valid;
    (void)decode_from_deltas(a, k, dx, dy, dw, dh, im0, im1, im2, &valid);

    unsigned int srt;
    if (valid) {
        unsigned int b = __float_as_uint(sc);
        srt = (b & 0x80000000u) ? ~b : (b | 0x80000000u);
    } else {
        srt = 0x007FFFFFu;   // flip(-inf)
    }
    g_srt[t] = srt;
    atomicAdd(&g_z.hist[srt >> 16], 1u);
}

// ---------------- K2: suffix table + threshold + candidate count ----------------
__global__ void k_thresh() {
    __shared__ unsigned int s[256];
    __shared__ unsigned int S2[256];
    __shared__ int gsel;
    __shared__ unsigned int above_s;
    int t = threadIdx.x;
    unsigned int sum = 0;
    const uint4* h4 = (const uint4*)g_z.hist;
#pragma unroll 8
    for (int b = 0; b < 64; b++) {
        uint4 v = h4[t * 64 + b];
        sum += v.x + v.y + v.z + v.w;
    }
    s[t] = sum;
    __syncthreads();
    for (int off = 1; off < 256; off <<= 1) {
        unsigned int v = (t + off < 256) ? s[t + off] : 0u;
        __syncthreads();
        s[t] += v;
        __syncthreads();
    }
    S2[t] = s[t];
    __syncthreads();

    // full per-bucket suffix table
    {
        unsigned int run = (t == 255) ? 0u : S2[t + 1];
        uint4* s4 = (uint4*)g_sfx;
#pragma unroll 4
        for (int q = 63; q >= 0; q--) {
            int idx4 = t * 64 + q;
            uint4 h = h4[idx4];
            uint4 o;
            o.w = run; run += h.w;
            o.z = run; run += h.z;
            o.y = run; run += h.y;
            o.x = run; run += h.x;
            s4[idx4] = o;
        }
    }

    unsigned int nxt = (t == 255) ? 0u : S2[t + 1];
    if (S2[t] >= TOPN && nxt < TOPN) { gsel = t; above_s = nxt; }
    __syncthreads();
    int g = gsel;
    unsigned int above = above_s;
    unsigned int fv = g_z.hist[g * 256 + t];
    __syncthreads();
    s[t] = fv;
    __syncthreads();
    for (int off = 1; off < 256; off <<= 1) {
        unsigned int v = (t + off < 256) ? s[t + off] : 0u;
        __syncthreads();
        s[t] += v;
        __syncthreads();
    }
    unsigned int nxt2 = (t == 255) ? 0u : s[t + 1];
    if (above + s[t] >= TOPN && above + nxt2 < TOPN) {
        g_thresh = (unsigned int)(g * 256 + t);
        g_cand_count = above + s[t];
    }
}

// ---------------- K3: compact candidates into bucket-ordered slots ----------------
__global__ void k_compact() {
    int t = blockIdx.x * blockDim.x + threadIdx.x;
    if (t >= NTOT) return;
    unsigned int srt = g_srt[t];
    unsigned int b = srt >> 16;
    if (b >= g_thresh) {
        int a = t / HW;
        int k = t - a * HW;
        int i_ref = k * NA + a;
        unsigned long long key =
            ((unsigned long long)srt << 32) | (0xFFFFFFFFu - (unsigned int)i_ref);
        unsigned int end = g_sfx[b - 1];                 // b >= thresh >= 1
        unsigned int old = atomicSub(&g_z.hist[b], 1u);  // counts down
        unsigned int slot = end - old;                   // bucket base .. end-1
        if (slot < CAND_MAX) g_cand[slot] = key;
    }
}

// ---------------- K4: in-bucket exact rank + decode + scatter ----------------
__global__ void k_ranksc(const float* __restrict__ deltas,
                         const float* __restrict__ im_info) {
    unsigned int C = g_cand_count;
    if (C > CAND_MAX) C = CAND_MAX;
    int i = blockIdx.x * blockDim.x + threadIdx.x;
    if (i >= (int)C) return;
    unsigned long long mykey = g_cand[i];
    unsigned int b = (unsigned int)(mykey >> 48);

    // hoist independent loads (decode inputs) ahead of the rank loop
    unsigned int idx = 0xFFFFFFFFu - (unsigned int)(mykey & 0xFFFFFFFFull);
    int a = idx % NA;
    int k = idx / NA;
    float dx = __ldg(&deltas[(4*a + 0) * HW + k]);
    float dy = __ldg(&deltas[(4*a + 1) * HW + k]);
    float dw = __ldg(&deltas[(4*a + 2) * HW + k]);
    float dh = __ldg(&deltas[(4*a + 3) * HW + k]);
    float im0 = __ldg(&im_info[0]), im1 = __ldg(&im_info[1]), im2 = __ldg(&im_info[2]);
    unsigned int base = g_sfx[b];
    unsigned int end = g_sfx[b - 1];
    if (end > C) end = C;

    unsigned int rank = base;
    for (unsigned int j = base; j < end; j++)
        rank += (g_cand[j] > mykey) ? 1u : 0u;

    if (rank < TOPN) {
        bool valid;
        float4 box = decode_from_deltas(a, k, dx, dy, dw, dh, im0, im1, im2, &valid);
        g_top_boxes[rank] = box;
        bool vkey = ((unsigned int)(mykey >> 32)) > 0x007FFFFFu;
        if (!vkey) atomicOr(&g_z.sup[rank >> 6], 1ull << (rank & 63));
    }
}

// ---------------- K5: NMS bitmask, triangular 1-D grid ----------------
__global__ void k_mask() {
    int lin = blockIdx.x;
    // decode lin -> (bi, bj) with bj >= bi ; T(i) = i*NB - i*(i-1)/2
    float f = 2.f * NB + 1.f;
    int bi = (int)((f - sqrtf(f * f - 8.f * (float)lin)) * 0.5f);
    while (bi > 0 && (bi * NB - (bi * (bi - 1)) / 2) > lin) bi--;
    while (((bi + 1) * NB - ((bi + 1) * bi) / 2) <= lin) bi++;
    int bj = bi + (lin - (bi * NB - (bi * (bi - 1)) / 2));

    int t = threadIdx.x;
    int i = bi * 64 + t;
    __shared__ float4 bb[64];
    __shared__ float ar[64];
    int jg0 = bj * 64 + t;
    if (jg0 < TOPN) {
        float4 b = g_top_boxes[jg0];
        bb[t] = b;
        ar[t] = (b.z - b.x) * (b.w - b.y);
    } else {
        bb[t] = make_float4(0.f, 0.f, 0.f, 0.f);
        ar[t] = 0.f;
    }
    __syncthreads();
    if (i >= TOPN) return;
    float4 bi_box = g_top_boxes[i];
    float area_i = (bi_box.z - bi_box.x) * (bi_box.w - bi_box.y);
    unsigned long long m = 0ull;
#pragma unroll 4
    for (int jj = 0; jj < 64; jj++) {
        int jg = bj * 64 + jj;
        float4 bj_box = bb[jj];
        float ix1 = fmaxf(bi_box.x, bj_box.x);
        float iy1 = fmaxf(bi_box.y, bj_box.y);
        float ix2 = fminf(bi_box.z, bj_box.z);
        float iy2 = fminf(bi_box.w, bj_box.w);
        float inter = fmaxf(ix2 - ix1, 0.f) * fmaxf(iy2 - iy1, 0.f);
        float denom = fmaxf(area_i + ar[jj] - inter, 1e-9f);
        float iou = inter / denom;
        if (iou > 0.7f && jg > i && jg < TOPN) m |= (1ull << jj);
    }
    g_mask[(size_t)i * NB + bj] = m;
}

// ---------------- K6: greedy collect, sparse predicated prefetch ----------
// Control flow uniform across block (branch data identical per thread).
__global__ void __launch_bounds__(CTH) k_collect(float* __restrict__ out) {
    __shared__ unsigned long long remv[NB];
    __shared__ int klist[POSTN];
    extern __shared__ unsigned long long tiles[];  // 2 * TILE_WORDS
    int tid = threadIdx.x;

    for (int t = tid; t < POSTN * 5; t += CTH) out[t] = 0.f;  // d_out is poisoned
    for (int t = tid; t < NB; t += CTH) {
        unsigned long long m = g_z.sup[t];
        if (t == NB - 1) m |= 0xFFFF000000000000ull;   // bits 48..63 (>= 6000)
        remv[t] = m;
    }
    __syncthreads();

    // prefetch tile 0 (rows not already suppressed)
    {
        unsigned long long rv = remv[0];
        for (int t = tid; t < 64 * NB; t += CTH) {
            int r = t / NB, w = t - r * NB;
            if (!((rv >> r) & 1ull))
                cp_async8(&tiles[t], &g_mask[(size_t)r * NB + w]);
        }
        cp_async_commit();
    }
    cp_async_wait0();
    __syncthreads();

    int kept = 0;
    for (int ib = 0; ib < NB; ib++) {
        unsigned long long* tile = tiles + (size_t)(ib & 1) * TILE_WORDS;
        // predicated prefetch of next tile: suppression only grows, so rows
        // dead in remv[ib+1] now can never be picked later.
        if (ib + 1 < NB) {
            int nb2 = ib + 1;
            int wcnt2 = NB - nb2;
            int rows2 = TOPN - nb2 * 64; if (rows2 > 64) rows2 = 64;
            unsigned long long rv = remv[nb2];
            unsigned long long* dst = tiles + (size_t)(nb2 & 1) * TILE_WORDS;
            for (int t = tid; t < rows2 * wcnt2; t += CTH) {
                int r = t / wcnt2, w = t - r * wcnt2;
                if (!((rv >> r) & 1ull))
                    cp_async8(&dst[t], &g_mask[(size_t)(nb2 * 64 + r) * NB + nb2 + w]);
            }
        }
        cp_async_commit();

        int wcnt = NB - ib;
        unsigned long long rcur = remv[ib];
        unsigned long long acc = 0ull;
        int w = tid;                       // this thread owns word ib+w (w<wcnt)
        while (true) {
            unsigned long long avail = ~rcur;
            if (avail == 0ull) break;
            int bit = __ffsll((long long)avail) - 1;
            if (tid == 0) klist[kept] = ib * 64 + bit;
            kept++;
            rcur |= tile[bit * wcnt] | (1ull << bit);      // self word + mark done
            if (w > 0 && w < wcnt) acc |= tile[bit * wcnt + w];
            if (kept >= POSTN) break;
        }
        if (w > 0 && w < wcnt) remv[ib + w] |= acc;
        if (kept >= POSTN) break;
        cp_async_wait0();
        __syncthreads();
    }

    cp_async_wait0();
    __syncthreads();
    // grid-stride: kept can exceed blockDim assumptions; never index by tid alone
    for (int t = tid; t < kept; t += CTH) {
        int idx = klist[t];
        float4 b = g_top_boxes[idx];
        float* row = out + t * 5;
        row[0] = 0.f; row[1] = b.x; row[2] = b.y; row[3] = b.z; row[4] = b.w;
    }
}

extern "C" void kernel_launch(void* const* d_in, const int* in_sizes, int n_in,
                              void* d_out, int out_size) {
    const float* scores  = (const float*)d_in[0];
    const float* deltas  = (const float*)d_in[1];
    const float* im_info = (const float*)d_in[2];
    float* out = (float*)d_out;

    void* p;
    cudaGetSymbolAddress(&p, g_z);
    cudaMemsetAsync(p, 0, sizeof(ZeroBlock));

    k_score_box<<<(NTOT + 255) / 256, 256>>>(scores, deltas, im_info);
    k_thresh<<<1, 256>>>();
    k_compact<<<(NTOT + 255) / 256, 256>>>();
    k_ranksc<<<CAND_MAX / 64, 64>>>(deltas, im_info);
    k_mask<<<NTRI, 64>>>();

    size_t csh = (size_t)2 * TILE_WORDS * sizeof(unsigned long long);
    cudaFuncSetAttribute(k_collect, cudaFuncAttributeMaxDynamicSharedMemorySize, (int)csh);
    k_collect<<<1, CTH, csh>>>(out);
}